// round 5
// baseline (speedup 1.0000x reference)
#include <cuda_runtime.h>
#include <math.h>

#define S_LEN 2048
#define BATCH 2
#define HID   2048
#define NH    32
#define NKV   8
#define HD    64
#define M_TOK (BATCH * S_LEN)   // 4096 tokens
#define KVD   (NKV * HD)        // 512

// Scratch (no cudaMalloc allowed)
__device__ float g_Q[M_TOK * HID];
__device__ float g_K[M_TOK * KVD];
__device__ float g_V[M_TOK * KVD];
__device__ float g_A[M_TOK * HID];

// ---------------------------------------------------------------------------
// fp32 SGEMM body: C[M,N] = A[M,K] * B[K,N], row-major.
// 128x128 block tile, BK=16, 256 threads, 8x8 per thread.
// Register-staged double buffer: LDG->regs issued before compute; compute on
// the current smem buffer hides load latency; then regs->smem, one sync/tile.
// Requires M%128==0, N%128==0, K%16==0.
// ---------------------------------------------------------------------------
__device__ __forceinline__ void sgemm_body(const float* __restrict__ A,
                                           const float* __restrict__ B,
                                           float* __restrict__ C,
                                           int M, int N, int K,
                                           int bx, int by) {
    __shared__ float As[2][16][128];   // As[buf][k][m]  (A transposed)
    __shared__ float Bs[2][16][128];   // Bs[buf][k][n]

    const int tx   = threadIdx.x;
    const int row0 = by * 128;
    const int col0 = bx * 128;
    const int tr   = (tx >> 4) << 3;   // 0..120
    const int tc   = (tx & 15) << 3;   // 0..120
    const int ar   = tx >> 2;          // 0..63  (A rows ar, ar+64)
    const int ac   = (tx & 3) << 2;    // 0,4,8,12
    const int br   = tx >> 5;          // 0..7   (B rows br, br+8)
    const int bc   = (tx & 31) << 2;   // 0..124

    const float* Ap0 = A + (size_t)(row0 + ar) * K + ac;
    const float* Ap1 = A + (size_t)(row0 + ar + 64) * K + ac;
    const float* Bp0 = B + (size_t)br * N + col0 + bc;
    const float* Bp1 = B + (size_t)(br + 8) * N + col0 + bc;

    float acc[8][8];
#pragma unroll
    for (int i = 0; i < 8; i++)
#pragma unroll
        for (int j = 0; j < 8; j++) acc[i][j] = 0.f;

    // prologue: tile 0 -> buffer 0
    {
        float4 a0 = *(const float4*)(Ap0);
        float4 a1 = *(const float4*)(Ap1);
        float4 b0 = *(const float4*)(Bp0);
        float4 b1 = *(const float4*)(Bp1);
        As[0][ac + 0][ar] = a0.x; As[0][ac + 1][ar] = a0.y;
        As[0][ac + 2][ar] = a0.z; As[0][ac + 3][ar] = a0.w;
        As[0][ac + 0][ar + 64] = a1.x; As[0][ac + 1][ar + 64] = a1.y;
        As[0][ac + 2][ar + 64] = a1.z; As[0][ac + 3][ar + 64] = a1.w;
        *(float4*)&Bs[0][br][bc]     = b0;
        *(float4*)&Bs[0][br + 8][bc] = b1;
    }
    __syncthreads();

    int buf = 0;
    for (int k0 = 0; k0 < K; k0 += 16) {
        const bool has_next = (k0 + 16) < K;
        float4 na0, na1, nb0, nb1;
        if (has_next) {
            na0 = *(const float4*)(Ap0 + k0 + 16);
            na1 = *(const float4*)(Ap1 + k0 + 16);
            nb0 = *(const float4*)(Bp0 + (size_t)(k0 + 16) * N);
            nb1 = *(const float4*)(Bp1 + (size_t)(k0 + 16) * N);
        }

#pragma unroll
        for (int kk = 0; kk < 16; kk++) {
            float4 a0 = *(float4*)&As[buf][kk][tr];
            float4 a1 = *(float4*)&As[buf][kk][tr + 4];
            float4 b0 = *(float4*)&Bs[buf][kk][tc];
            float4 b1 = *(float4*)&Bs[buf][kk][tc + 4];
            float ra[8] = {a0.x, a0.y, a0.z, a0.w, a1.x, a1.y, a1.z, a1.w};
            float rb[8] = {b0.x, b0.y, b0.z, b0.w, b1.x, b1.y, b1.z, b1.w};
#pragma unroll
            for (int i = 0; i < 8; i++)
#pragma unroll
                for (int j = 0; j < 8; j++) acc[i][j] += ra[i] * rb[j];
        }

        if (has_next) {
            const int nb = buf ^ 1;
            As[nb][ac + 0][ar] = na0.x; As[nb][ac + 1][ar] = na0.y;
            As[nb][ac + 2][ar] = na0.z; As[nb][ac + 3][ar] = na0.w;
            As[nb][ac + 0][ar + 64] = na1.x; As[nb][ac + 1][ar + 64] = na1.y;
            As[nb][ac + 2][ar + 64] = na1.z; As[nb][ac + 3][ar + 64] = na1.w;
            *(float4*)&Bs[nb][br][bc]     = nb0;
            *(float4*)&Bs[nb][br + 8][bc] = nb1;
            __syncthreads();
            buf = nb;
        }
    }

#pragma unroll
    for (int i = 0; i < 8; i++) {
        float* cp = C + (size_t)(row0 + tr + i) * N + col0 + tc;
        *(float4*)(cp)     = make_float4(acc[i][0], acc[i][1], acc[i][2], acc[i][3]);
        *(float4*)(cp + 4) = make_float4(acc[i][4], acc[i][5], acc[i][6], acc[i][7]);
    }
}

__global__ __launch_bounds__(256) void sgemm128(const float* __restrict__ A,
                                                const float* __restrict__ B,
                                                float* __restrict__ C,
                                                int M, int N, int K) {
    sgemm_body(A, B, C, M, N, K, blockIdx.x, blockIdx.y);
}

// Fused K+V projection: blockIdx.z selects weight/output pair. One launch,
// 256 CTAs instead of two serialized 128-CTA launches.
__global__ __launch_bounds__(256) void kvgemm(const float* __restrict__ X,
                                              const float* __restrict__ Wk,
                                              const float* __restrict__ Wv,
                                              float* __restrict__ Kb,
                                              float* __restrict__ Vb) {
    const float* B = blockIdx.z ? Wv : Wk;
    float*       C = blockIdx.z ? Vb : Kb;
    sgemm_body(X, B, C, M_TOK, KVD, HID, blockIdx.x, blockIdx.y);
}

// ---------------------------------------------------------------------------
// Fused RoPE in place for Q and K.
// out[i]    = x[i]*cos(a_i)    - x[i+32]*sin(a_i)
// out[i+32] = x[i+32]*cos(a_i) + x[i]*sin(a_i),  a_i = s * base^(-2i/64)
// ---------------------------------------------------------------------------
#define ROPE_Q_TOTAL (M_TOK * NH * 32)
#define ROPE_TOTAL   (M_TOK * (NH + NKV) * 32)

__global__ void rope_qk(float* __restrict__ Qx, float* __restrict__ Kx) {
    int idx = blockIdx.x * blockDim.x + threadIdx.x;
    if (idx >= ROPE_TOTAL) return;
    float* X;
    int nheads;
    if (idx < ROPE_Q_TOTAL) {
        X = Qx; nheads = NH;
    } else {
        X = Kx; nheads = NKV; idx -= ROPE_Q_TOTAL;
    }
    int i = idx & 31;
    int h = (idx >> 5) % nheads;
    int m = idx / (nheads * 32);
    int s = m & (S_LEN - 1);
    const float LOG2_BASE = 13.287712379549449f;   // log2(10000)
    float freq = exp2f(-(float)(2 * i) * (LOG2_BASE / 64.0f));
    float ang  = (float)s * freq;
    float sn, cs;
    sincosf(ang, &sn, &cs);
    float* row = X + (size_t)m * (nheads * HD) + h * HD;
    float x1 = row[i], x2 = row[i + 32];
    row[i]      = x1 * cs - x2 * sn;
    row[i + 32] = x2 * cs + x1 * sn;
}

// ---------------------------------------------------------------------------
// Causal flash attention, one q-row per thread, 128 q-rows per block.
// Q: [M_TOK, 2048] (heads packed), K/V: [M_TOK, 512], O: [M_TOK, 2048].
// GQA: head h uses kv head h/4. Scale 1/sqrt(64)=0.125 folded into q.
// Inner loops use explicit float4 smem reads (guaranteed LDS.128 broadcast).
// ---------------------------------------------------------------------------
__global__ __launch_bounds__(128) void attn_k(const float* __restrict__ Q,
                                              const float* __restrict__ K,
                                              const float* __restrict__ V,
                                              float* __restrict__ O) {
    __shared__ float Ks[16][64];
    __shared__ float Vs[16][64];
    const int tid = threadIdx.x;
    const int qi  = blockIdx.x * 128 + tid;       // query position in sequence
    const int h   = blockIdx.y;
    const int b   = blockIdx.z;
    const int kvh = h >> 2;

    float4 q[16];                                  // 64 floats as float4
    const float4* qp = (const float4*)(Q + (size_t)(b * S_LEN + qi) * HID + h * HD);
#pragma unroll
    for (int d4 = 0; d4 < 16; d4++) {
        float4 v = qp[d4];
        q[d4] = make_float4(v.x * 0.125f, v.y * 0.125f, v.z * 0.125f, v.w * 0.125f);
    }

    float4 acc[16];
#pragma unroll
    for (int d4 = 0; d4 < 16; d4++) acc[d4] = make_float4(0.f, 0.f, 0.f, 0.f);
    float mx = -1e30f, ls = 0.f;

    const int qmax   = blockIdx.x * 128 + 127;
    const int ntiles = (qmax >> 4) + 1;
    const int lr = tid >> 3;          // 0..15
    const int lc = (tid & 7) << 3;    // 0,8,...,56

    for (int t = 0; t < ntiles; t++) {
        const int kb = t << 4;
        const size_t grow = (size_t)(b * S_LEN + kb + lr) * KVD + kvh * HD + lc;
        *(float4*)&Ks[lr][lc]     = *(const float4*)(K + grow);
        *(float4*)&Ks[lr][lc + 4] = *(const float4*)(K + grow + 4);
        *(float4*)&Vs[lr][lc]     = *(const float4*)(V + grow);
        *(float4*)&Vs[lr][lc + 4] = *(const float4*)(V + grow + 4);
        __syncthreads();

        float sc[16];
#pragma unroll
        for (int j = 0; j < 16; j++) {
            const float4* kr = (const float4*)&Ks[j][0];
            float s = 0.f;
#pragma unroll
            for (int d4 = 0; d4 < 16; d4++) {
                float4 kv = kr[d4];
                s += q[d4].x * kv.x + q[d4].y * kv.y
                   + q[d4].z * kv.z + q[d4].w * kv.w;
            }
            sc[j] = (kb + j <= qi) ? s : -1e30f;
        }
        float tmax = sc[0];
#pragma unroll
        for (int j = 1; j < 16; j++) tmax = fmaxf(tmax, sc[j]);
        float mn   = fmaxf(mx, tmax);
        float corr = __expf(mx - mn);
        ls *= corr;
#pragma unroll
        for (int d4 = 0; d4 < 16; d4++) {
            acc[d4].x *= corr; acc[d4].y *= corr;
            acc[d4].z *= corr; acc[d4].w *= corr;
        }
#pragma unroll
        for (int j = 0; j < 16; j++) {
            float p = __expf(sc[j] - mn);
            ls += p;
            const float4* vr = (const float4*)&Vs[j][0];
#pragma unroll
            for (int d4 = 0; d4 < 16; d4++) {
                float4 vv = vr[d4];
                acc[d4].x += p * vv.x; acc[d4].y += p * vv.y;
                acc[d4].z += p * vv.z; acc[d4].w += p * vv.w;
            }
        }
        mx = mn;
        __syncthreads();
    }

    float inv = 1.0f / ls;
    float4* op = (float4*)(O + (size_t)(b * S_LEN + qi) * HID + h * HD);
#pragma unroll
    for (int d4 = 0; d4 < 16; d4++) {
        op[d4] = make_float4(acc[d4].x * inv, acc[d4].y * inv,
                             acc[d4].z * inv, acc[d4].w * inv);
    }
}

// ---------------------------------------------------------------------------
extern "C" void kernel_launch(void* const* d_in, const int* in_sizes, int n_in,
                              void* d_out, int out_size) {
    const float* X  = (const float*)d_in[0];
    // d_in[1] = attention_mask (exact causal -1e9) — implemented analytically.
    const float* Wq = (const float*)d_in[2];
    const float* Wk = (const float*)d_in[3];
    const float* Wv = (const float*)d_in[4];
    const float* Wo = (const float*)d_in[5];
    float* out = (float*)d_out;

    float *Qb, *Kb, *Vb, *Ab;
    cudaGetSymbolAddress((void**)&Qb, g_Q);
    cudaGetSymbolAddress((void**)&Kb, g_K);
    cudaGetSymbolAddress((void**)&Vb, g_V);
    cudaGetSymbolAddress((void**)&Ab, g_A);

    // Projections: Q, then fused K+V (one launch, 2x CTAs)
    sgemm128<<<dim3(HID / 128, M_TOK / 128), 256>>>(X, Wq, Qb, M_TOK, HID, HID);
    kvgemm<<<dim3(KVD / 128, M_TOK / 128, 2), 256>>>(X, Wk, Wv, Kb, Vb);

    // RoPE (in place on Q and K, single launch)
    rope_qk<<<(ROPE_TOTAL + 255) / 256, 256>>>(Qb, Kb);

    // Causal flash attention with GQA
    attn_k<<<dim3(S_LEN / 128, NH, BATCH), 128>>>(Qb, Kb, Vb, Ab);

    // Output projection
    sgemm128<<<dim3(HID / 128, M_TOK / 128), 256>>>(Ab, Wo, out, M_TOK, HID, HID);
}

// round 7
// speedup vs baseline: 1.4722x; 1.4722x over previous
#include <cuda_runtime.h>
#include <cuda_bf16.h>
#include <math.h>
#include <stdint.h>

#define S_LEN 2048
#define BATCH 2
#define HID   2048
#define NH    32
#define NKV   8
#define HD    64
#define M_TOK (BATCH * S_LEN)   // 4096 tokens
#define KVD   (NKV * HD)        // 512

// fp32 scratch
__device__ float g_Q[M_TOK * HID];
__device__ float g_K[M_TOK * KVD];
__device__ float g_V[M_TOK * KVD];
__device__ float g_A[M_TOK * HID];
// bf16 hi/lo split scratch
__device__ __nv_bfloat16 g_Xhi[M_TOK * HID], g_Xlo[M_TOK * HID];
__device__ __nv_bfloat16 g_Ahi[M_TOK * HID], g_Alo[M_TOK * HID];
__device__ __nv_bfloat16 g_Wqhi[HID * HID], g_Wqlo[HID * HID];
__device__ __nv_bfloat16 g_Wkhi[HID * KVD], g_Wklo[HID * KVD];
__device__ __nv_bfloat16 g_Wvhi[HID * KVD], g_Wvlo[HID * KVD];
__device__ __nv_bfloat16 g_Wohi[HID * HID], g_Wolo[HID * HID];

// ---------------------------------------------------------------------------
// fp32 -> (hi, lo) bf16 split.  x ~= hi + lo, lo captures next 8 mantissa bits.
// ---------------------------------------------------------------------------
__global__ void cvt_hilo(const float* __restrict__ s,
                         __nv_bfloat16* __restrict__ hi,
                         __nv_bfloat16* __restrict__ lo, int n4) {
    int i = blockIdx.x * blockDim.x + threadIdx.x;
    if (i >= n4) return;
    float4 v = ((const float4*)s)[i];
    __nv_bfloat16 h0 = __float2bfloat16_rn(v.x);
    __nv_bfloat16 h1 = __float2bfloat16_rn(v.y);
    __nv_bfloat16 h2 = __float2bfloat16_rn(v.z);
    __nv_bfloat16 h3 = __float2bfloat16_rn(v.w);
    __nv_bfloat16 l0 = __float2bfloat16_rn(v.x - __bfloat162float(h0));
    __nv_bfloat16 l1 = __float2bfloat16_rn(v.y - __bfloat162float(h1));
    __nv_bfloat16 l2 = __float2bfloat16_rn(v.z - __bfloat162float(h2));
    __nv_bfloat16 l3 = __float2bfloat16_rn(v.w - __bfloat162float(h3));
    __nv_bfloat162 hh0; hh0.x = h0; hh0.y = h1;
    __nv_bfloat162 hh1; hh1.x = h2; hh1.y = h3;
    __nv_bfloat162 ll0; ll0.x = l0; ll0.y = l1;
    __nv_bfloat162 ll1; ll1.x = l2; ll1.y = l3;
    ((__nv_bfloat162*)hi)[2 * i]     = hh0;
    ((__nv_bfloat162*)hi)[2 * i + 1] = hh1;
    ((__nv_bfloat162*)lo)[2 * i]     = ll0;
    ((__nv_bfloat162*)lo)[2 * i + 1] = ll1;
}

// ---------------------------------------------------------------------------
// mma.sync helpers
// ---------------------------------------------------------------------------
__device__ __forceinline__ void ldsm4(uint32_t* r, const void* p) {
    uint32_t a = (uint32_t)__cvta_generic_to_shared(p);
    asm volatile("ldmatrix.sync.aligned.m8n8.x4.shared.b16 {%0,%1,%2,%3}, [%4];"
                 : "=r"(r[0]), "=r"(r[1]), "=r"(r[2]), "=r"(r[3]) : "r"(a));
}
__device__ __forceinline__ void ldsm4t(uint32_t* r, const void* p) {
    uint32_t a = (uint32_t)__cvta_generic_to_shared(p);
    asm volatile("ldmatrix.sync.aligned.m8n8.x4.trans.shared.b16 {%0,%1,%2,%3}, [%4];"
                 : "=r"(r[0]), "=r"(r[1]), "=r"(r[2]), "=r"(r[3]) : "r"(a));
}
__device__ __forceinline__ void mma_bf16(float* c, const uint32_t* a, const uint32_t* b) {
    asm volatile(
        "mma.sync.aligned.m16n8k16.row.col.f32.bf16.bf16.f32 "
        "{%0,%1,%2,%3}, {%4,%5,%6,%7}, {%8,%9}, {%0,%1,%2,%3};"
        : "+f"(c[0]), "+f"(c[1]), "+f"(c[2]), "+f"(c[3])
        : "r"(a[0]), "r"(a[1]), "r"(a[2]), "r"(a[3]), "r"(b[0]), "r"(b[1]));
}

// ---------------------------------------------------------------------------
// bf16 split-GEMM: C[M,N](fp32) = (Ah+Al)[M,K] * (Bh+Bl)[K,N], 3-term split.
// CTA tile 128x128, BK=16, 256 threads = 8 warps (2m x 4n), warp tile 64x32.
// A smem [128][24] (pad), B smem [16][136] (pad).
// ---------------------------------------------------------------------------
#define APAD 24
#define BPAD 136

__device__ __forceinline__ void mma_gemm_body(
    const __nv_bfloat16* __restrict__ Ah, const __nv_bfloat16* __restrict__ Al,
    const __nv_bfloat16* __restrict__ Bh, const __nv_bfloat16* __restrict__ Bl,
    float* __restrict__ C, int N, int K, int bx, int by) {

    __shared__ __align__(16) __nv_bfloat16 Ah_s[2][128 * APAD];
    __shared__ __align__(16) __nv_bfloat16 Al_s[2][128 * APAD];
    __shared__ __align__(16) __nv_bfloat16 Bh_s[2][16 * BPAD];
    __shared__ __align__(16) __nv_bfloat16 Bl_s[2][16 * BPAD];

    const int t    = threadIdx.x;
    const int lane = t & 31;
    const int warp = t >> 5;
    const int wm   = (warp & 1) * 64;    // warp m offset in tile
    const int wn   = (warp >> 1) * 32;   // warp n offset in tile
    const int row0 = by * 128;
    const int col0 = bx * 128;

    // global load coords (one uint4 = 8 bf16 per matrix per thread per tile)
    const int am = t >> 1, ak = (t & 1) * 8;    // A: 128 rows x 16 k
    const int bk = t >> 4, bn = (t & 15) * 8;   // B: 16 rows x 128 n
    const __nv_bfloat16* gAh = Ah + (size_t)(row0 + am) * K + ak;
    const __nv_bfloat16* gAl = Al + (size_t)(row0 + am) * K + ak;
    const __nv_bfloat16* gBh = Bh + (size_t)bk * N + col0 + bn;
    const __nv_bfloat16* gBl = Bl + (size_t)bk * N + col0 + bn;

    float acc[4][4][4];
#pragma unroll
    for (int i = 0; i < 4; i++)
#pragma unroll
        for (int j = 0; j < 4; j++)
#pragma unroll
            for (int r = 0; r < 4; r++) acc[i][j][r] = 0.f;

    // prologue: k-tile 0 -> buffer 0
    {
        uint4 vah = *(const uint4*)gAh;
        uint4 val = *(const uint4*)gAl;
        uint4 vbh = *(const uint4*)gBh;
        uint4 vbl = *(const uint4*)gBl;
        *(uint4*)&Ah_s[0][am * APAD + ak] = vah;
        *(uint4*)&Al_s[0][am * APAD + ak] = val;
        *(uint4*)&Bh_s[0][bk * BPAD + bn] = vbh;
        *(uint4*)&Bl_s[0][bk * BPAD + bn] = vbl;
    }
    __syncthreads();

    // ldmatrix lane addressing
    const int lrow = lane & 15;          // matrix row within frag
    const int lcol = (lane >> 4) * 8;    // 0 or 8: column half
    const int a_off = (wm + lrow) * APAD + lcol;           // + mf*16*APAD
    const int b_off = lrow * BPAD + wn + lcol;             // + nfp*16

    const int niter = K / 16;
    int buf = 0;
    for (int kt = 0; kt < niter; kt++) {
        const bool hn = (kt + 1) < niter;
        uint4 nah, nal, nbh, nbl;
        if (hn) {
            const int k0 = (kt + 1) * 16;
            nah = *(const uint4*)(gAh + k0);
            nal = *(const uint4*)(gAl + k0);
            nbh = *(const uint4*)(gBh + (size_t)k0 * N);
            nbl = *(const uint4*)(gBl + (size_t)k0 * N);
        }

        // ---- compute on current buffer ----
        uint32_t ah[4][4];
#pragma unroll
        for (int mf = 0; mf < 4; mf++)
            ldsm4(ah[mf], &Ah_s[buf][a_off + mf * 16 * APAD]);
        uint32_t bh[4][2];
#pragma unroll
        for (int nfp = 0; nfp < 2; nfp++) {
            uint32_t r[4];
            ldsm4t(r, &Bh_s[buf][b_off + nfp * 16]);
            bh[nfp * 2][0] = r[0]; bh[nfp * 2][1] = r[1];
            bh[nfp * 2 + 1][0] = r[2]; bh[nfp * 2 + 1][1] = r[3];
        }
#pragma unroll
        for (int mf = 0; mf < 4; mf++)
#pragma unroll
            for (int nf = 0; nf < 4; nf++)
                mma_bf16(acc[mf][nf], ah[mf], bh[nf]);   // hi*hi

        uint32_t bl[4][2];
#pragma unroll
        for (int nfp = 0; nfp < 2; nfp++) {
            uint32_t r[4];
            ldsm4t(r, &Bl_s[buf][b_off + nfp * 16]);
            bl[nfp * 2][0] = r[0]; bl[nfp * 2][1] = r[1];
            bl[nfp * 2 + 1][0] = r[2]; bl[nfp * 2 + 1][1] = r[3];
        }
#pragma unroll
        for (int mf = 0; mf < 4; mf++)
#pragma unroll
            for (int nf = 0; nf < 4; nf++)
                mma_bf16(acc[mf][nf], ah[mf], bl[nf]);   // hi*lo

        uint32_t al[4][4];
#pragma unroll
        for (int mf = 0; mf < 4; mf++)
            ldsm4(al[mf], &Al_s[buf][a_off + mf * 16 * APAD]);
#pragma unroll
        for (int mf = 0; mf < 4; mf++)
#pragma unroll
            for (int nf = 0; nf < 4; nf++)
                mma_bf16(acc[mf][nf], al[mf], bh[nf]);   // lo*hi

        // ---- stage next tile ----
        if (hn) {
            const int nb = buf ^ 1;
            *(uint4*)&Ah_s[nb][am * APAD + ak] = nah;
            *(uint4*)&Al_s[nb][am * APAD + ak] = nal;
            *(uint4*)&Bh_s[nb][bk * BPAD + bn] = nbh;
            *(uint4*)&Bl_s[nb][bk * BPAD + bn] = nbl;
            __syncthreads();
            buf = nb;
        }
    }

    // epilogue
    const int gid = lane >> 2, tg = lane & 3;
#pragma unroll
    for (int mf = 0; mf < 4; mf++) {
#pragma unroll
        for (int nf = 0; nf < 4; nf++) {
            float* p0 = C + (size_t)(row0 + wm + mf * 16 + gid) * N
                          + col0 + wn + nf * 8 + tg * 2;
            float* p1 = p0 + 8 * (size_t)N;
            float2 v0 = make_float2(acc[mf][nf][0], acc[mf][nf][1]);
            float2 v1 = make_float2(acc[mf][nf][2], acc[mf][nf][3]);
            *(float2*)p0 = v0;
            *(float2*)p1 = v1;
        }
    }
}

__global__ __launch_bounds__(256, 1) void mma_gemm(
    const __nv_bfloat16* __restrict__ Ah, const __nv_bfloat16* __restrict__ Al,
    const __nv_bfloat16* __restrict__ Bh, const __nv_bfloat16* __restrict__ Bl,
    float* __restrict__ C, int N, int K) {
    mma_gemm_body(Ah, Al, Bh, Bl, C, N, K, blockIdx.x, blockIdx.y);
}

// Fused K+V projection: blockIdx.z selects weight/output pair.
__global__ __launch_bounds__(256, 1) void mma_gemm_kv(
    const __nv_bfloat16* __restrict__ Ah, const __nv_bfloat16* __restrict__ Al,
    const __nv_bfloat16* __restrict__ Wkh, const __nv_bfloat16* __restrict__ Wkl,
    const __nv_bfloat16* __restrict__ Wvh, const __nv_bfloat16* __restrict__ Wvl,
    float* __restrict__ Kb, float* __restrict__ Vb) {
    const __nv_bfloat16* Bh = blockIdx.z ? Wvh : Wkh;
    const __nv_bfloat16* Bl = blockIdx.z ? Wvl : Wkl;
    float* C = blockIdx.z ? Vb : Kb;
    mma_gemm_body(Ah, Al, Bh, Bl, C, KVD, HID, blockIdx.x, blockIdx.y);
}

// ---------------------------------------------------------------------------
// Fused RoPE in place for Q and K.
// ---------------------------------------------------------------------------
#define ROPE_Q_TOTAL (M_TOK * NH * 32)
#define ROPE_TOTAL   (M_TOK * (NH + NKV) * 32)

__global__ void rope_qk(float* __restrict__ Qx, float* __restrict__ Kx) {
    int idx = blockIdx.x * blockDim.x + threadIdx.x;
    if (idx >= ROPE_TOTAL) return;
    float* X;
    int nheads;
    if (idx < ROPE_Q_TOTAL) {
        X = Qx; nheads = NH;
    } else {
        X = Kx; nheads = NKV; idx -= ROPE_Q_TOTAL;
    }
    int i = idx & 31;
    int h = (idx >> 5) % nheads;
    int m = idx / (nheads * 32);
    int s = m & (S_LEN - 1);
    const float LOG2_BASE = 13.287712379549449f;   // log2(10000)
    float freq = exp2f(-(float)(2 * i) * (LOG2_BASE / 64.0f));
    float ang  = (float)s * freq;
    float sn, cs;
    sincosf(ang, &sn, &cs);
    float* row = X + (size_t)m * (nheads * HD) + h * HD;
    float x1 = row[i], x2 = row[i + 32];
    row[i]      = x1 * cs - x2 * sn;
    row[i + 32] = x2 * cs + x1 * sn;
}

// ---------------------------------------------------------------------------
// Causal flash attention (fp32, one q-row per thread).
// ---------------------------------------------------------------------------
__global__ __launch_bounds__(128) void attn_k(const float* __restrict__ Q,
                                              const float* __restrict__ K,
                                              const float* __restrict__ V,
                                              float* __restrict__ O) {
    __shared__ float Ks[16][64];
    __shared__ float Vs[16][64];
    const int tid = threadIdx.x;
    const int qi  = blockIdx.x * 128 + tid;
    const int h   = blockIdx.y;
    const int b   = blockIdx.z;
    const int kvh = h >> 2;

    float4 q[16];
    const float4* qp = (const float4*)(Q + (size_t)(b * S_LEN + qi) * HID + h * HD);
#pragma unroll
    for (int d4 = 0; d4 < 16; d4++) {
        float4 v = qp[d4];
        q[d4] = make_float4(v.x * 0.125f, v.y * 0.125f, v.z * 0.125f, v.w * 0.125f);
    }

    float4 acc[16];
#pragma unroll
    for (int d4 = 0; d4 < 16; d4++) acc[d4] = make_float4(0.f, 0.f, 0.f, 0.f);
    float mx = -1e30f, ls = 0.f;

    const int qmax   = blockIdx.x * 128 + 127;
    const int ntiles = (qmax >> 4) + 1;
    const int lr = tid >> 3;
    const int lc = (tid & 7) << 3;

    for (int t = 0; t < ntiles; t++) {
        const int kb = t << 4;
        const size_t grow = (size_t)(b * S_LEN + kb + lr) * KVD + kvh * HD + lc;
        *(float4*)&Ks[lr][lc]     = *(const float4*)(K + grow);
        *(float4*)&Ks[lr][lc + 4] = *(const float4*)(K + grow + 4);
        *(float4*)&Vs[lr][lc]     = *(const float4*)(V + grow);
        *(float4*)&Vs[lr][lc + 4] = *(const float4*)(V + grow + 4);
        __syncthreads();

        float sc[16];
#pragma unroll
        for (int j = 0; j < 16; j++) {
            const float4* kr = (const float4*)&Ks[j][0];
            float s = 0.f;
#pragma unroll
            for (int d4 = 0; d4 < 16; d4++) {
                float4 kv = kr[d4];
                s += q[d4].x * kv.x + q[d4].y * kv.y
                   + q[d4].z * kv.z + q[d4].w * kv.w;
            }
            sc[j] = (kb + j <= qi) ? s : -1e30f;
        }
        float tmax = sc[0];
#pragma unroll
        for (int j = 1; j < 16; j++) tmax = fmaxf(tmax, sc[j]);
        float mn   = fmaxf(mx, tmax);
        float corr = __expf(mx - mn);
        ls *= corr;
#pragma unroll
        for (int d4 = 0; d4 < 16; d4++) {
            acc[d4].x *= corr; acc[d4].y *= corr;
            acc[d4].z *= corr; acc[d4].w *= corr;
        }
#pragma unroll
        for (int j = 0; j < 16; j++) {
            float p = __expf(sc[j] - mn);
            ls += p;
            const float4* vr = (const float4*)&Vs[j][0];
#pragma unroll
            for (int d4 = 0; d4 < 16; d4++) {
                float4 vv = vr[d4];
                acc[d4].x += p * vv.x; acc[d4].y += p * vv.y;
                acc[d4].z += p * vv.z; acc[d4].w += p * vv.w;
            }
        }
        mx = mn;
        __syncthreads();
    }

    float inv = 1.0f / ls;
    float4* op = (float4*)(O + (size_t)(b * S_LEN + qi) * HID + h * HD);
#pragma unroll
    for (int d4 = 0; d4 < 16; d4++) {
        op[d4] = make_float4(acc[d4].x * inv, acc[d4].y * inv,
                             acc[d4].z * inv, acc[d4].w * inv);
    }
}

// ---------------------------------------------------------------------------
extern "C" void kernel_launch(void* const* d_in, const int* in_sizes, int n_in,
                              void* d_out, int out_size) {
    const float* X  = (const float*)d_in[0];
    // d_in[1] = attention_mask (exact causal -1e9) — implemented analytically.
    const float* Wq = (const float*)d_in[2];
    const float* Wk = (const float*)d_in[3];
    const float* Wv = (const float*)d_in[4];
    const float* Wo = (const float*)d_in[5];
    float* out = (float*)d_out;

    float *Qb, *Kb, *Vb, *Ab;
    cudaGetSymbolAddress((void**)&Qb, g_Q);
    cudaGetSymbolAddress((void**)&Kb, g_K);
    cudaGetSymbolAddress((void**)&Vb, g_V);
    cudaGetSymbolAddress((void**)&Ab, g_A);
    __nv_bfloat16 *Xhi, *Xlo, *Ahi, *Alo, *Wqhi, *Wqlo, *Wkhi, *Wklo,
                  *Wvhi, *Wvlo, *Wohi, *Wolo;
    cudaGetSymbolAddress((void**)&Xhi, g_Xhi);  cudaGetSymbolAddress((void**)&Xlo, g_Xlo);
    cudaGetSymbolAddress((void**)&Ahi, g_Ahi);  cudaGetSymbolAddress((void**)&Alo, g_Alo);
    cudaGetSymbolAddress((void**)&Wqhi, g_Wqhi); cudaGetSymbolAddress((void**)&Wqlo, g_Wqlo);
    cudaGetSymbolAddress((void**)&Wkhi, g_Wkhi); cudaGetSymbolAddress((void**)&Wklo, g_Wklo);
    cudaGetSymbolAddress((void**)&Wvhi, g_Wvhi); cudaGetSymbolAddress((void**)&Wvlo, g_Wvlo);
    cudaGetSymbolAddress((void**)&Wohi, g_Wohi); cudaGetSymbolAddress((void**)&Wolo, g_Wolo);

    // hi/lo conversions
    {
        int n4;
        n4 = (M_TOK * HID) / 4; cvt_hilo<<<(n4 + 255) / 256, 256>>>(X,  Xhi,  Xlo,  n4);
        n4 = (HID * HID) / 4;   cvt_hilo<<<(n4 + 255) / 256, 256>>>(Wq, Wqhi, Wqlo, n4);
        n4 = (HID * KVD) / 4;   cvt_hilo<<<(n4 + 255) / 256, 256>>>(Wk, Wkhi, Wklo, n4);
        n4 = (HID * KVD) / 4;   cvt_hilo<<<(n4 + 255) / 256, 256>>>(Wv, Wvhi, Wvlo, n4);
        n4 = (HID * HID) / 4;   cvt_hilo<<<(n4 + 255) / 256, 256>>>(Wo, Wohi, Wolo, n4);
    }

    // Projections (tensor-core bf16 split GEMMs)
    mma_gemm<<<dim3(HID / 128, M_TOK / 128), 256>>>(Xhi, Xlo, Wqhi, Wqlo, Qb, HID, HID);
    mma_gemm_kv<<<dim3(KVD / 128, M_TOK / 128, 2), 256>>>(Xhi, Xlo, Wkhi, Wklo,
                                                          Wvhi, Wvlo, Kb, Vb);

    // RoPE (in place on Q and K)
    rope_qk<<<(ROPE_TOTAL + 255) / 256, 256>>>(Qb, Kb);

    // Causal flash attention with GQA (fp32)
    attn_k<<<dim3(S_LEN / 128, NH, BATCH), 128>>>(Qb, Kb, Vb, Ab);

    // Output projection
    {
        int n4 = (M_TOK * HID) / 4;
        cvt_hilo<<<(n4 + 255) / 256, 256>>>(Ab, Ahi, Alo, n4);
    }
    mma_gemm<<<dim3(HID / 128, M_TOK / 128), 256>>>(Ahi, Alo, Wohi, Wolo, out, HID, HID);
}

// round 9
// speedup vs baseline: 2.8771x; 1.9543x over previous
#include <cuda_runtime.h>
#include <cuda_bf16.h>
#include <math.h>
#include <stdint.h>

#define S_LEN 2048
#define BATCH 2
#define HID   2048
#define NH    32
#define NKV   8
#define HD    64
#define M_TOK (BATCH * S_LEN)   // 4096 tokens
#define KVD   (NKV * HD)        // 512

// fp32 scratch
__device__ float g_Q[M_TOK * HID];
__device__ float g_K[M_TOK * KVD];
__device__ float g_V[M_TOK * KVD];
// bf16 hi/lo split scratch
__device__ __nv_bfloat16 g_Xhi[M_TOK * HID], g_Xlo[M_TOK * HID];
__device__ __nv_bfloat16 g_Ahi[M_TOK * HID], g_Alo[M_TOK * HID];
__device__ __nv_bfloat16 g_Qhi[M_TOK * HID], g_Qlo[M_TOK * HID];
__device__ __nv_bfloat16 g_Khi[M_TOK * KVD], g_Klo[M_TOK * KVD];
__device__ __nv_bfloat16 g_Vhi[M_TOK * KVD], g_Vlo[M_TOK * KVD];
__device__ __nv_bfloat16 g_Wqhi[HID * HID], g_Wqlo[HID * HID];
__device__ __nv_bfloat16 g_Wkhi[HID * KVD], g_Wklo[HID * KVD];
__device__ __nv_bfloat16 g_Wvhi[HID * KVD], g_Wvlo[HID * KVD];
__device__ __nv_bfloat16 g_Wohi[HID * HID], g_Wolo[HID * HID];

// ---------------------------------------------------------------------------
// fp32 -> (hi, lo) bf16 split.
// ---------------------------------------------------------------------------
__global__ void cvt_hilo(const float* __restrict__ s,
                         __nv_bfloat16* __restrict__ hi,
                         __nv_bfloat16* __restrict__ lo, int n4) {
    int i = blockIdx.x * blockDim.x + threadIdx.x;
    if (i >= n4) return;
    float4 v = ((const float4*)s)[i];
    __nv_bfloat16 h0 = __float2bfloat16_rn(v.x);
    __nv_bfloat16 h1 = __float2bfloat16_rn(v.y);
    __nv_bfloat16 h2 = __float2bfloat16_rn(v.z);
    __nv_bfloat16 h3 = __float2bfloat16_rn(v.w);
    __nv_bfloat16 l0 = __float2bfloat16_rn(v.x - __bfloat162float(h0));
    __nv_bfloat16 l1 = __float2bfloat16_rn(v.y - __bfloat162float(h1));
    __nv_bfloat16 l2 = __float2bfloat16_rn(v.z - __bfloat162float(h2));
    __nv_bfloat16 l3 = __float2bfloat16_rn(v.w - __bfloat162float(h3));
    __nv_bfloat162 hh0; hh0.x = h0; hh0.y = h1;
    __nv_bfloat162 hh1; hh1.x = h2; hh1.y = h3;
    __nv_bfloat162 ll0; ll0.x = l0; ll0.y = l1;
    __nv_bfloat162 ll1; ll1.x = l2; ll1.y = l3;
    ((__nv_bfloat162*)hi)[2 * i]     = hh0;
    ((__nv_bfloat162*)hi)[2 * i + 1] = hh1;
    ((__nv_bfloat162*)lo)[2 * i]     = ll0;
    ((__nv_bfloat162*)lo)[2 * i + 1] = ll1;
}

// ---------------------------------------------------------------------------
// mma.sync helpers (hardware-validated in round 7)
// ---------------------------------------------------------------------------
__device__ __forceinline__ void ldsm4(uint32_t* r, const void* p) {
    uint32_t a = (uint32_t)__cvta_generic_to_shared(p);
    asm volatile("ldmatrix.sync.aligned.m8n8.x4.shared.b16 {%0,%1,%2,%3}, [%4];"
                 : "=r"(r[0]), "=r"(r[1]), "=r"(r[2]), "=r"(r[3]) : "r"(a));
}
__device__ __forceinline__ void ldsm4t(uint32_t* r, const void* p) {
    uint32_t a = (uint32_t)__cvta_generic_to_shared(p);
    asm volatile("ldmatrix.sync.aligned.m8n8.x4.trans.shared.b16 {%0,%1,%2,%3}, [%4];"
                 : "=r"(r[0]), "=r"(r[1]), "=r"(r[2]), "=r"(r[3]) : "r"(a));
}
__device__ __forceinline__ void mma_bf16(float* c, const uint32_t* a, const uint32_t* b) {
    asm volatile(
        "mma.sync.aligned.m16n8k16.row.col.f32.bf16.bf16.f32 "
        "{%0,%1,%2,%3}, {%4,%5,%6,%7}, {%8,%9}, {%0,%1,%2,%3};"
        : "+f"(c[0]), "+f"(c[1]), "+f"(c[2]), "+f"(c[3])
        : "r"(a[0]), "r"(a[1]), "r"(a[2]), "r"(a[3]), "r"(b[0]), "r"(b[1]));
}

// exp on the FMA pipe (no MUFU): exp(x) for x <= 0, ~1e-6 rel accuracy.
__device__ __forceinline__ float expap(float x) {
    float t = fmaxf(x * 1.4426950408889634f, -30.0f);
    int i = __float2int_rn(t);
    float f = t - (float)i;
    float p = 1.3333558e-3f;
    p = fmaf(p, f, 9.6181291e-3f);
    p = fmaf(p, f, 5.5504109e-2f);
    p = fmaf(p, f, 2.4022651e-1f);
    p = fmaf(p, f, 6.9314718e-1f);
    p = fmaf(p, f, 1.0f);
    return __int_as_float((i + 127) << 23) * p;
}

__device__ __forceinline__ uint32_t packbf(float lo, float hi) {
    uint16_t l = __bfloat16_as_ushort(__float2bfloat16_rn(lo));
    uint16_t h = __bfloat16_as_ushort(__float2bfloat16_rn(hi));
    return ((uint32_t)h << 16) | (uint32_t)l;
}

// ---------------------------------------------------------------------------
// bf16 split-GEMM (validated round 7). CTA 128x128, BK=16, 8 warps.
// ---------------------------------------------------------------------------
#define APAD 24
#define BPAD 136

__device__ __forceinline__ void mma_gemm_body(
    const __nv_bfloat16* __restrict__ Ah, const __nv_bfloat16* __restrict__ Al,
    const __nv_bfloat16* __restrict__ Bh, const __nv_bfloat16* __restrict__ Bl,
    float* __restrict__ C, int N, int K, int bx, int by) {

    __shared__ __align__(16) __nv_bfloat16 Ah_s[2][128 * APAD];
    __shared__ __align__(16) __nv_bfloat16 Al_s[2][128 * APAD];
    __shared__ __align__(16) __nv_bfloat16 Bh_s[2][16 * BPAD];
    __shared__ __align__(16) __nv_bfloat16 Bl_s[2][16 * BPAD];

    const int t    = threadIdx.x;
    const int lane = t & 31;
    const int warp = t >> 5;
    const int wm   = (warp & 1) * 64;
    const int wn   = (warp >> 1) * 32;
    const int row0 = by * 128;
    const int col0 = bx * 128;

    const int am = t >> 1, ak = (t & 1) * 8;
    const int bk = t >> 4, bn = (t & 15) * 8;
    const __nv_bfloat16* gAh = Ah + (size_t)(row0 + am) * K + ak;
    const __nv_bfloat16* gAl = Al + (size_t)(row0 + am) * K + ak;
    const __nv_bfloat16* gBh = Bh + (size_t)bk * N + col0 + bn;
    const __nv_bfloat16* gBl = Bl + (size_t)bk * N + col0 + bn;

    float acc[4][4][4];
#pragma unroll
    for (int i = 0; i < 4; i++)
#pragma unroll
        for (int j = 0; j < 4; j++)
#pragma unroll
            for (int r = 0; r < 4; r++) acc[i][j][r] = 0.f;

    {
        *(uint4*)&Ah_s[0][am * APAD + ak] = *(const uint4*)gAh;
        *(uint4*)&Al_s[0][am * APAD + ak] = *(const uint4*)gAl;
        *(uint4*)&Bh_s[0][bk * BPAD + bn] = *(const uint4*)gBh;
        *(uint4*)&Bl_s[0][bk * BPAD + bn] = *(const uint4*)gBl;
    }
    __syncthreads();

    const int lrow = lane & 15;
    const int lcol = (lane >> 4) * 8;
    const int a_off = (wm + lrow) * APAD + lcol;
    const int b_off = lrow * BPAD + wn + lcol;

    const int niter = K / 16;
    int buf = 0;
    for (int kt = 0; kt < niter; kt++) {
        const bool hn = (kt + 1) < niter;
        uint4 nah, nal, nbh, nbl;
        if (hn) {
            const int k0 = (kt + 1) * 16;
            nah = *(const uint4*)(gAh + k0);
            nal = *(const uint4*)(gAl + k0);
            nbh = *(const uint4*)(gBh + (size_t)k0 * N);
            nbl = *(const uint4*)(gBl + (size_t)k0 * N);
        }

        uint32_t ah[4][4];
#pragma unroll
        for (int mf = 0; mf < 4; mf++)
            ldsm4(ah[mf], &Ah_s[buf][a_off + mf * 16 * APAD]);
        uint32_t bh[4][2];
#pragma unroll
        for (int nfp = 0; nfp < 2; nfp++) {
            uint32_t r[4];
            ldsm4t(r, &Bh_s[buf][b_off + nfp * 16]);
            bh[nfp * 2][0] = r[0]; bh[nfp * 2][1] = r[1];
            bh[nfp * 2 + 1][0] = r[2]; bh[nfp * 2 + 1][1] = r[3];
        }
#pragma unroll
        for (int mf = 0; mf < 4; mf++)
#pragma unroll
            for (int nf = 0; nf < 4; nf++)
                mma_bf16(acc[mf][nf], ah[mf], bh[nf]);

        uint32_t bl[4][2];
#pragma unroll
        for (int nfp = 0; nfp < 2; nfp++) {
            uint32_t r[4];
            ldsm4t(r, &Bl_s[buf][b_off + nfp * 16]);
            bl[nfp * 2][0] = r[0]; bl[nfp * 2][1] = r[1];
            bl[nfp * 2 + 1][0] = r[2]; bl[nfp * 2 + 1][1] = r[3];
        }
#pragma unroll
        for (int mf = 0; mf < 4; mf++)
#pragma unroll
            for (int nf = 0; nf < 4; nf++)
                mma_bf16(acc[mf][nf], ah[mf], bl[nf]);

        uint32_t al[4][4];
#pragma unroll
        for (int mf = 0; mf < 4; mf++)
            ldsm4(al[mf], &Al_s[buf][a_off + mf * 16 * APAD]);
#pragma unroll
        for (int mf = 0; mf < 4; mf++)
#pragma unroll
            for (int nf = 0; nf < 4; nf++)
                mma_bf16(acc[mf][nf], al[mf], bh[nf]);

        if (hn) {
            const int nb = buf ^ 1;
            *(uint4*)&Ah_s[nb][am * APAD + ak] = nah;
            *(uint4*)&Al_s[nb][am * APAD + ak] = nal;
            *(uint4*)&Bh_s[nb][bk * BPAD + bn] = nbh;
            *(uint4*)&Bl_s[nb][bk * BPAD + bn] = nbl;
            __syncthreads();
            buf = nb;
        }
    }

    const int gid = lane >> 2, tg = lane & 3;
#pragma unroll
    for (int mf = 0; mf < 4; mf++) {
#pragma unroll
        for (int nf = 0; nf < 4; nf++) {
            float* p0 = C + (size_t)(row0 + wm + mf * 16 + gid) * N
                          + col0 + wn + nf * 8 + tg * 2;
            float* p1 = p0 + 8 * (size_t)N;
            *(float2*)p0 = make_float2(acc[mf][nf][0], acc[mf][nf][1]);
            *(float2*)p1 = make_float2(acc[mf][nf][2], acc[mf][nf][3]);
        }
    }
}

__global__ __launch_bounds__(256, 1) void mma_gemm(
    const __nv_bfloat16* __restrict__ Ah, const __nv_bfloat16* __restrict__ Al,
    const __nv_bfloat16* __restrict__ Bh, const __nv_bfloat16* __restrict__ Bl,
    float* __restrict__ C, int N, int K) {
    mma_gemm_body(Ah, Al, Bh, Bl, C, N, K, blockIdx.x, blockIdx.y);
}

__global__ __launch_bounds__(256, 1) void mma_gemm_kv(
    const __nv_bfloat16* __restrict__ Ah, const __nv_bfloat16* __restrict__ Al,
    const __nv_bfloat16* __restrict__ Wkh, const __nv_bfloat16* __restrict__ Wkl,
    const __nv_bfloat16* __restrict__ Wvh, const __nv_bfloat16* __restrict__ Wvl,
    float* __restrict__ Kb, float* __restrict__ Vb) {
    const __nv_bfloat16* Bh = blockIdx.z ? Wvh : Wkh;
    const __nv_bfloat16* Bl = blockIdx.z ? Wvl : Wkl;
    float* C = blockIdx.z ? Vb : Kb;
    mma_gemm_body(Ah, Al, Bh, Bl, C, KVD, HID, blockIdx.x, blockIdx.y);
}

// ---------------------------------------------------------------------------
// RoPE + bf16 hi/lo conversion for Q (scaled by 0.125) and K.
// ---------------------------------------------------------------------------
#define ROPE_Q_TOTAL (M_TOK * NH * 32)
#define ROPE_TOTAL   (M_TOK * (NH + NKV) * 32)

__global__ void rope_cvt(const float* __restrict__ Qf, const float* __restrict__ Kf,
                         __nv_bfloat16* __restrict__ Qhi, __nv_bfloat16* __restrict__ Qlo,
                         __nv_bfloat16* __restrict__ Khi, __nv_bfloat16* __restrict__ Klo) {
    int idx = blockIdx.x * blockDim.x + threadIdx.x;
    if (idx >= ROPE_TOTAL) return;
    const float* X; __nv_bfloat16 *H, *L; int nheads; float scale;
    if (idx < ROPE_Q_TOTAL) { X = Qf; H = Qhi; L = Qlo; nheads = NH; scale = 0.125f; }
    else { idx -= ROPE_Q_TOTAL; X = Kf; H = Khi; L = Klo; nheads = NKV; scale = 1.0f; }
    int i = idx & 31;
    int hh = (idx >> 5) % nheads;
    int m = idx / (nheads * 32);
    int s = m & (S_LEN - 1);
    const float LOG2_BASE = 13.287712379549449f;
    float freq = exp2f(-(float)(2 * i) * (LOG2_BASE / 64.0f));
    float ang  = (float)s * freq;
    float sn, cs;
    sincosf(ang, &sn, &cs);
    const float* row = X + (size_t)m * (nheads * HD) + hh * HD;
    float x1 = row[i], x2 = row[i + 32];
    float y1 = (x1 * cs - x2 * sn) * scale;
    float y2 = (x2 * cs + x1 * sn) * scale;
    size_t o = (size_t)m * (nheads * HD) + hh * HD;
    __nv_bfloat16 h1 = __float2bfloat16_rn(y1);
    __nv_bfloat16 h2 = __float2bfloat16_rn(y2);
    H[o + i]      = h1;
    L[o + i]      = __float2bfloat16_rn(y1 - __bfloat162float(h1));
    H[o + i + 32] = h2;
    L[o + i + 32] = __float2bfloat16_rn(y2 - __bfloat162float(h2));
}

// ---------------------------------------------------------------------------
// Tensor-core causal flash attention.
// CTA = one (b,h), 128 q rows, 256 threads = 8 warps x 16 rows.
// QK: qh*kh + qh*kl + ql*kh ; PV: ph*vh + pl*vh + ph*vl (fp32 accum).
// Output written directly as bf16 hi/lo for the Wo GEMM.
// ---------------------------------------------------------------------------
#define KT 64
#define DP 72   // smem row stride in bf16 (144 B: ldmatrix conflict-free)

__global__ __launch_bounds__(256, 1) void attn_mma(
    const __nv_bfloat16* __restrict__ Qh, const __nv_bfloat16* __restrict__ Ql,
    const __nv_bfloat16* __restrict__ Kh, const __nv_bfloat16* __restrict__ Kl,
    const __nv_bfloat16* __restrict__ Vh, const __nv_bfloat16* __restrict__ Vl,
    __nv_bfloat16* __restrict__ Oh, __nv_bfloat16* __restrict__ Ol) {

    __shared__ __align__(16) __nv_bfloat16 smA[128 * DP];  // Q-hi stage, then K hi/lo
    __shared__ __align__(16) __nv_bfloat16 smB[128 * DP];  // Q-lo stage, then V hi/lo

    const int t    = threadIdx.x;
    const int lane = t & 31;
    const int w    = t >> 5;
    const int gid  = lane >> 2, tg = lane & 3;
    const int qb   = blockIdx.x * 128;
    const int h    = blockIdx.y;
    const int b    = blockIdx.z;
    const int kvh  = h >> 2;

    // ---- stage Q tile (128 x 64, hi/lo) and extract A-frags ----
    const size_t qbase = ((size_t)(b * S_LEN + qb)) * HID + (size_t)h * HD;
#pragma unroll
    for (int r = 0; r < 4; r++) {
        int i = r * 256 + t;            // 0..1023 uint4
        int row = i >> 3, c = (i & 7) * 8;
        *(uint4*)&smA[row * DP + c] = *(const uint4*)(Qh + qbase + (size_t)row * HID + c);
        *(uint4*)&smB[row * DP + c] = *(const uint4*)(Ql + qbase + (size_t)row * HID + c);
    }
    __syncthreads();

    uint32_t qhf[4][4], qlf[4][4];
    {
        const int lrow = lane & 15, lcol = (lane >> 4) * 8;
#pragma unroll
        for (int dc = 0; dc < 4; dc++) {
            ldsm4(qhf[dc], &smA[(w * 16 + lrow) * DP + dc * 16 + lcol]);
            ldsm4(qlf[dc], &smB[(w * 16 + lrow) * DP + dc * 16 + lcol]);
        }
    }
    __syncthreads();

    __nv_bfloat16* Khs = smA;
    __nv_bfloat16* Kls = smA + 64 * DP;
    __nv_bfloat16* Vhs = smB;
    __nv_bfloat16* Vls = smB + 64 * DP;

    float oc[8][4];
#pragma unroll
    for (int d = 0; d < 8; d++)
#pragma unroll
        for (int r = 0; r < 4; r++) oc[d][r] = 0.f;
    float m0 = -1e30f, m1 = -1e30f, l0 = 0.f, l1 = 0.f;

    const int q0 = qb + w * 16 + gid;
    const int q1 = q0 + 8;
    const int warp_qmin = qb + w * 16;
    const int warp_qmax = warp_qmin + 15;
    const int ntiles = qb / 64 + 2;

    // lane constants for K B-frag ldsm4 (non-trans):
    const int kselr = (lane & 7) + ((lane >> 4) & 1) * 8;
    const int kseld = ((lane >> 3) & 1) * 8;
    // V ldsm4t addressing (same pattern as GEMM B)
    const int vrow = lane & 15, vcol = (lane >> 4) * 8;

    for (int tt = 0; tt < ntiles; tt++) {
        const int kt0 = tt * KT;
        // cooperative K/V tile load (64 x 64, 4 arrays, 2 uint4/thread each)
#pragma unroll
        for (int rep = 0; rep < 2; rep++) {
            int j = rep * 256 + t;       // 0..511
            int row = j >> 3, c = (j & 7) * 8;
            size_t g = ((size_t)(b * S_LEN + kt0 + row)) * KVD + (size_t)kvh * HD + c;
            int so = row * DP + c;
            *(uint4*)&Khs[so] = *(const uint4*)(Kh + g);
            *(uint4*)&Kls[so] = *(const uint4*)(Kl + g);
            *(uint4*)&Vhs[so] = *(const uint4*)(Vh + g);
            *(uint4*)&Vls[so] = *(const uint4*)(Vl + g);
        }
        __syncthreads();

        if (kt0 <= warp_qmax) {
            // ---- S = Q K^T (3-term split) ----
            float sc[8][4];
#pragma unroll
            for (int nf = 0; nf < 8; nf++)
#pragma unroll
                for (int r = 0; r < 4; r++) sc[nf][r] = 0.f;

#pragma unroll
            for (int dc = 0; dc < 4; dc++) {
#pragma unroll
                for (int kg = 0; kg < 4; kg++) {
                    uint32_t khr[4], klr[4];
                    const int koff = (kg * 16 + kselr) * DP + dc * 16 + kseld;
                    ldsm4(khr, &Khs[koff]);
                    ldsm4(klr, &Kls[koff]);
                    mma_bf16(sc[2 * kg],     qhf[dc], khr);
                    mma_bf16(sc[2 * kg + 1], qhf[dc], khr + 2);
                    mma_bf16(sc[2 * kg],     qhf[dc], klr);
                    mma_bf16(sc[2 * kg + 1], qhf[dc], klr + 2);
                    mma_bf16(sc[2 * kg],     qlf[dc], khr);
                    mma_bf16(sc[2 * kg + 1], qlf[dc], khr + 2);
                }
            }

            // causal mask (boundary tiles only)
            if (kt0 + KT - 1 > warp_qmin) {
#pragma unroll
                for (int nf = 0; nf < 8; nf++) {
                    int k0 = kt0 + nf * 8 + 2 * tg;
                    if (k0     > q0) sc[nf][0] = -1e30f;
                    if (k0 + 1 > q0) sc[nf][1] = -1e30f;
                    if (k0     > q1) sc[nf][2] = -1e30f;
                    if (k0 + 1 > q1) sc[nf][3] = -1e30f;
                }
            }

            // ---- online softmax ----
            float rm0 = -1e30f, rm1 = -1e30f;
#pragma unroll
            for (int nf = 0; nf < 8; nf++) {
                rm0 = fmaxf(rm0, fmaxf(sc[nf][0], sc[nf][1]));
                rm1 = fmaxf(rm1, fmaxf(sc[nf][2], sc[nf][3]));
            }
            rm0 = fmaxf(rm0, __shfl_xor_sync(0xffffffffu, rm0, 1));
            rm0 = fmaxf(rm0, __shfl_xor_sync(0xffffffffu, rm0, 2));
            rm1 = fmaxf(rm1, __shfl_xor_sync(0xffffffffu, rm1, 1));
            rm1 = fmaxf(rm1, __shfl_xor_sync(0xffffffffu, rm1, 2));
            float nm0 = fmaxf(m0, rm0), nm1 = fmaxf(m1, rm1);
            float f0 = expap(m0 - nm0), f1 = expap(m1 - nm1);
            m0 = nm0; m1 = nm1;
            l0 *= f0; l1 *= f1;
#pragma unroll
            for (int d = 0; d < 8; d++) {
                oc[d][0] *= f0; oc[d][1] *= f0;
                oc[d][2] *= f1; oc[d][3] *= f1;
            }

            uint32_t pah[4][4], pal[4][4];
#pragma unroll
            for (int nf = 0; nf < 8; nf++) {
                float p0 = expap(sc[nf][0] - m0);
                float p1 = expap(sc[nf][1] - m0);
                float p2 = expap(sc[nf][2] - m1);
                float p3 = expap(sc[nf][3] - m1);
                l0 += p0 + p1; l1 += p2 + p3;
                float p0h = __bfloat162float(__float2bfloat16_rn(p0));
                float p1h = __bfloat162float(__float2bfloat16_rn(p1));
                float p2h = __bfloat162float(__float2bfloat16_rn(p2));
                float p3h = __bfloat162float(__float2bfloat16_rn(p3));
                int kc = nf >> 1, hf = (nf & 1) * 2;
                pah[kc][hf]     = packbf(p0, p1);
                pah[kc][hf + 1] = packbf(p2, p3);
                pal[kc][hf]     = packbf(p0 - p0h, p1 - p1h);
                pal[kc][hf + 1] = packbf(p2 - p2h, p3 - p3h);
            }

            // ---- O += P V (3-term split) ----
#pragma unroll
            for (int kc = 0; kc < 4; kc++) {
#pragma unroll
                for (int dg = 0; dg < 4; dg++) {
                    uint32_t vhr[4], vlr[4];
                    const int voff = (kc * 16 + vrow) * DP + dg * 16 + vcol;
                    ldsm4t(vhr, &Vhs[voff]);
                    ldsm4t(vlr, &Vls[voff]);
                    mma_bf16(oc[2 * dg],     pah[kc], vhr);
                    mma_bf16(oc[2 * dg + 1], pah[kc], vhr + 2);
                    mma_bf16(oc[2 * dg],     pal[kc], vhr);
                    mma_bf16(oc[2 * dg + 1], pal[kc], vhr + 2);
                    mma_bf16(oc[2 * dg],     pah[kc], vlr);
                    mma_bf16(oc[2 * dg + 1], pah[kc], vlr + 2);
                }
            }
        }
        __syncthreads();
    }

    // ---- finalize: quad-reduce l, normalize, write bf16 hi/lo ----
    l0 += __shfl_xor_sync(0xffffffffu, l0, 1);
    l0 += __shfl_xor_sync(0xffffffffu, l0, 2);
    l1 += __shfl_xor_sync(0xffffffffu, l1, 1);
    l1 += __shfl_xor_sync(0xffffffffu, l1, 2);
    float i0 = 1.f / l0, i1 = 1.f / l1;

    const size_t o0 = ((size_t)(b * S_LEN + q0)) * HID + (size_t)h * HD;
    const size_t o1 = ((size_t)(b * S_LEN + q1)) * HID + (size_t)h * HD;
#pragma unroll
    for (int df = 0; df < 8; df++) {
        int cidx = df * 8 + 2 * tg;
        float a0 = oc[df][0] * i0, a1 = oc[df][1] * i0;
        float b0 = oc[df][2] * i1, b1 = oc[df][3] * i1;
        float a0h = __bfloat162float(__float2bfloat16_rn(a0));
        float a1h = __bfloat162float(__float2bfloat16_rn(a1));
        float b0h = __bfloat162float(__float2bfloat16_rn(b0));
        float b1h = __bfloat162float(__float2bfloat16_rn(b1));
        *(uint32_t*)(Oh + o0 + cidx) = packbf(a0, a1);
        *(uint32_t*)(Ol + o0 + cidx) = packbf(a0 - a0h, a1 - a1h);
        *(uint32_t*)(Oh + o1 + cidx) = packbf(b0, b1);
        *(uint32_t*)(Ol + o1 + cidx) = packbf(b0 - b0h, b1 - b1h);
    }
}

// ---------------------------------------------------------------------------
extern "C" void kernel_launch(void* const* d_in, const int* in_sizes, int n_in,
                              void* d_out, int out_size) {
    const float* X  = (const float*)d_in[0];
    // d_in[1] = attention_mask (exact causal -1e9) — implemented analytically.
    const float* Wq = (const float*)d_in[2];
    const float* Wk = (const float*)d_in[3];
    const float* Wv = (const float*)d_in[4];
    const float* Wo = (const float*)d_in[5];
    float* out = (float*)d_out;

    float *Qb, *Kb, *Vb;
    cudaGetSymbolAddress((void**)&Qb, g_Q);
    cudaGetSymbolAddress((void**)&Kb, g_K);
    cudaGetSymbolAddress((void**)&Vb, g_V);
    __nv_bfloat16 *Xhi, *Xlo, *Ahi, *Alo, *Qhi, *Qlo, *Khi, *Klo, *Vhi, *Vlo;
    __nv_bfloat16 *Wqhi, *Wqlo, *Wkhi, *Wklo, *Wvhi, *Wvlo, *Wohi, *Wolo;
    cudaGetSymbolAddress((void**)&Xhi, g_Xhi);  cudaGetSymbolAddress((void**)&Xlo, g_Xlo);
    cudaGetSymbolAddress((void**)&Ahi, g_Ahi);  cudaGetSymbolAddress((void**)&Alo, g_Alo);
    cudaGetSymbolAddress((void**)&Qhi, g_Qhi);  cudaGetSymbolAddress((void**)&Qlo, g_Qlo);
    cudaGetSymbolAddress((void**)&Khi, g_Khi);  cudaGetSymbolAddress((void**)&Klo, g_Klo);
    cudaGetSymbolAddress((void**)&Vhi, g_Vhi);  cudaGetSymbolAddress((void**)&Vlo, g_Vlo);
    cudaGetSymbolAddress((void**)&Wqhi, g_Wqhi); cudaGetSymbolAddress((void**)&Wqlo, g_Wqlo);
    cudaGetSymbolAddress((void**)&Wkhi, g_Wkhi); cudaGetSymbolAddress((void**)&Wklo, g_Wklo);
    cudaGetSymbolAddress((void**)&Wvhi, g_Wvhi); cudaGetSymbolAddress((void**)&Wvlo, g_Wvlo);
    cudaGetSymbolAddress((void**)&Wohi, g_Wohi); cudaGetSymbolAddress((void**)&Wolo, g_Wolo);

    // hi/lo conversions of inputs
    {
        int n4;
        n4 = (M_TOK * HID) / 4; cvt_hilo<<<(n4 + 255) / 256, 256>>>(X,  Xhi,  Xlo,  n4);
        n4 = (HID * HID) / 4;   cvt_hilo<<<(n4 + 255) / 256, 256>>>(Wq, Wqhi, Wqlo, n4);
        n4 = (HID * KVD) / 4;   cvt_hilo<<<(n4 + 255) / 256, 256>>>(Wk, Wkhi, Wklo, n4);
        n4 = (HID * KVD) / 4;   cvt_hilo<<<(n4 + 255) / 256, 256>>>(Wv, Wvhi, Wvlo, n4);
        n4 = (HID * HID) / 4;   cvt_hilo<<<(n4 + 255) / 256, 256>>>(Wo, Wohi, Wolo, n4);
    }

    // Projections (tensor-core split GEMMs, fp32 out)
    mma_gemm<<<dim3(HID / 128, M_TOK / 128), 256>>>(Xhi, Xlo, Wqhi, Wqlo, Qb, HID, HID);
    mma_gemm_kv<<<dim3(KVD / 128, M_TOK / 128, 2), 256>>>(Xhi, Xlo, Wkhi, Wklo,
                                                          Wvhi, Wvlo, Kb, Vb);

    // RoPE + hi/lo conversion (Q scaled by 1/sqrt(64)); V conversion
    rope_cvt<<<(ROPE_TOTAL + 255) / 256, 256>>>(Qb, Kb, Qhi, Qlo, Khi, Klo);
    {
        int n4 = (M_TOK * KVD) / 4;
        cvt_hilo<<<(n4 + 255) / 256, 256>>>(Vb, Vhi, Vlo, n4);
    }

    // Tensor-core causal flash attention -> bf16 hi/lo activations
    attn_mma<<<dim3(S_LEN / 128, NH, BATCH), 256>>>(Qhi, Qlo, Khi, Klo,
                                                    Vhi, Vlo, Ahi, Alo);

    // Output projection
    mma_gemm<<<dim3(HID / 128, M_TOK / 128), 256>>>(Ahi, Alo, Wohi, Wolo, out, HID, HID);
}